// round 3
// baseline (speedup 1.0000x reference)
#include <cuda_runtime.h>
#include <cuda_bf16.h>
#include <math.h>

#define M_ROWS 32768
#define H_DIM  1024
#define O_DIM  929
#define TEMP_INV 1.25f   /* 1/0.8 */
#define EPS_G 1e-20f

// Scratch: two 32768x1024 fp32 buffers (128 MB each), static device globals.
__device__ float g_h1[(size_t)M_ROWS * H_DIM];
__device__ float g_h2[(size_t)M_ROWS * H_DIM];

__constant__ int c_seg_off[13] = {0, 29, 31, 32, 38, 45, 104, 105, 129, 205, 916, 919, 928};
__constant__ int c_seg_num[13] = {29, 2, 1, 6, 7, 59, 1, 24, 76, 711, 3, 9, 1};

// ---------------------------------------------------------------------------
// Tiled SGEMM: C[M,N] = act(A[M,K] @ B[K,N] + bias[N])
// BM=BN=128, BK=8, 256 threads, 8x8 per-thread microtile.
// ACT: 0 = none, 1 = ELU, 2 = sigmoid
// Requires: M % 128 == 0, K % 8 == 0. N arbitrary (bounds-checked).
// ---------------------------------------------------------------------------
template <int ACT>
__global__ __launch_bounds__(256)
void gemm_act_kernel(const float* __restrict__ A,
                     const float* __restrict__ B,
                     const float* __restrict__ bias,
                     float* __restrict__ C,
                     int M, int N, int K)
{
    constexpr int BM = 128, BN = 128, BK = 8;
    __shared__ float As[BK][BM + 4];
    __shared__ float Bs[BK][BN];

    const int tid   = threadIdx.x;
    const int a_row = tid >> 1;            // 0..127
    const int a_col = (tid & 1) << 2;      // 0 or 4
    const int b_row = tid >> 5;            // 0..7
    const int b_col = (tid & 31) << 2;     // 0..124
    const int tm    = (tid >> 4) << 3;     // 0..120
    const int tn    = (tid & 15) << 3;     // 0..120

    const size_t aBase = (size_t)(blockIdx.y * BM + a_row) * K + a_col;
    const int    nBase = blockIdx.x * BN;
    const bool   n_vec = ((N & 3) == 0);   // float4-safe B rows?

    float acc[8][8];
#pragma unroll
    for (int i = 0; i < 8; i++)
#pragma unroll
        for (int j = 0; j < 8; j++) acc[i][j] = 0.f;

    for (int k0 = 0; k0 < K; k0 += BK) {
        // --- load A tile (always in-bounds, 16B aligned since K%4==0) ---
        float4 av = *reinterpret_cast<const float4*>(A + aBase + k0);
        As[a_col + 0][a_row] = av.x;
        As[a_col + 1][a_row] = av.y;
        As[a_col + 2][a_row] = av.z;
        As[a_col + 3][a_row] = av.w;

        // --- load B tile (bounds + alignment handled) ---
        const float* Brow = B + (size_t)(k0 + b_row) * N;
        const int gc = nBase + b_col;
        float4 bv;
        if (n_vec && (gc + 4 <= N)) {
            bv = *reinterpret_cast<const float4*>(Brow + gc);
        } else {
            bv.x = (gc + 0 < N) ? Brow[gc + 0] : 0.f;
            bv.y = (gc + 1 < N) ? Brow[gc + 1] : 0.f;
            bv.z = (gc + 2 < N) ? Brow[gc + 2] : 0.f;
            bv.w = (gc + 3 < N) ? Brow[gc + 3] : 0.f;
        }
        Bs[b_row][b_col + 0] = bv.x;
        Bs[b_row][b_col + 1] = bv.y;
        Bs[b_row][b_col + 2] = bv.z;
        Bs[b_row][b_col + 3] = bv.w;

        __syncthreads();

#pragma unroll
        for (int kk = 0; kk < BK; kk++) {
            float ar[8], br[8];
#pragma unroll
            for (int i = 0; i < 8; i++) ar[i] = As[kk][tm + i];
#pragma unroll
            for (int j = 0; j < 8; j++) br[j] = Bs[kk][tn + j];
#pragma unroll
            for (int i = 0; i < 8; i++)
#pragma unroll
                for (int j = 0; j < 8; j++)
                    acc[i][j] += ar[i] * br[j];
        }
        __syncthreads();
    }

    // --- epilogue: bias + activation + store ---
#pragma unroll
    for (int i = 0; i < 8; i++) {
        const size_t crow = (size_t)(blockIdx.y * BM + tm + i) * N;
#pragma unroll
        for (int j = 0; j < 8; j++) {
            const int col = nBase + tn + j;
            if (col < N) {
                float v = acc[i][j] + bias[col];
                if (ACT == 1) v = (v > 0.f) ? v : expm1f(v);
                else if (ACT == 2) v = 1.f / (1.f + expf(-v));
                C[crow + col] = v;
            }
        }
    }
}

// ---------------------------------------------------------------------------
// Block reductions (256 threads, 8 warps)
// ---------------------------------------------------------------------------
__device__ __forceinline__ float block_reduce_max(float v, volatile float* red)
{
#pragma unroll
    for (int off = 16; off > 0; off >>= 1)
        v = fmaxf(v, __shfl_xor_sync(0xffffffffu, v, off));
    if ((threadIdx.x & 31) == 0) red[threadIdx.x >> 5] = v;
    __syncthreads();
    if (threadIdx.x < 32) {
        float w = (threadIdx.x < 8) ? red[threadIdx.x] : -3.4e38f;
#pragma unroll
        for (int off = 4; off > 0; off >>= 1)
            w = fmaxf(w, __shfl_xor_sync(0xffffffffu, w, off));
        if (threadIdx.x == 0) red[32] = w;
    }
    __syncthreads();
    return red[32];
}

__device__ __forceinline__ float block_reduce_sum(float v, volatile float* red)
{
#pragma unroll
    for (int off = 16; off > 0; off >>= 1)
        v += __shfl_xor_sync(0xffffffffu, v, off);
    if ((threadIdx.x & 31) == 0) red[threadIdx.x >> 5] = v;
    __syncthreads();
    if (threadIdx.x < 32) {
        float w = (threadIdx.x < 8) ? red[threadIdx.x] : 0.f;
#pragma unroll
        for (int off = 4; off > 0; off >>= 1)
            w += __shfl_xor_sync(0xffffffffu, w, off);
        if (threadIdx.x == 0) red[32] = w;
    }
    __syncthreads();
    return red[32];
}

// ---------------------------------------------------------------------------
// In-place segmented Gumbel-softmax over each row of `out` (32768 x 929).
// One 256-thread block per row. Segments with n==1 are left untouched (they
// already hold the raw logit). For n>1: y = (logit + g)/TEMP, softmax(y).
// g = -log(-log(u + EPS) + EPS).
// ---------------------------------------------------------------------------
__global__ __launch_bounds__(256)
void gumbel_softmax_kernel(float* __restrict__ out, const float* __restrict__ u)
{
    __shared__ float s[O_DIM];
    __shared__ float red[40];

    const int row = blockIdx.x;
    const int tid = threadIdx.x;
    float* orow = out + (size_t)row * O_DIM;
    const float* urow = u + (size_t)row * O_DIM;

    for (int i = tid; i < O_DIM; i += 256) s[i] = orow[i];
    __syncthreads();

#pragma unroll
    for (int seg = 0; seg < 13; seg++) {
        const int n   = c_seg_num[seg];
        const int off = c_seg_off[seg];
        if (n == 1) continue;  // raw logit already in out

        // pass 1: gumbel perturb + temperature, local max
        float lmax = -3.4e38f;
        for (int i = tid; i < n; i += 256) {
            const float uu = urow[off + i];
            const float g  = -logf(-logf(uu + EPS_G) + EPS_G);
            const float y  = (s[off + i] + g) * TEMP_INV;
            s[off + i] = y;
            lmax = fmaxf(lmax, y);
        }
        const float m = block_reduce_max(lmax, red);

        // pass 2: exp + local sum (same thread touches same indices)
        float lsum = 0.f;
        for (int i = tid; i < n; i += 256) {
            const float e = expf(s[off + i] - m);
            s[off + i] = e;
            lsum += e;
        }
        const float tot = block_reduce_sum(lsum, red);
        const float inv = 1.f / tot;

        // pass 3: normalize + store
        for (int i = tid; i < n; i += 256)
            orow[off + i] = s[off + i] * inv;
    }
}

// ---------------------------------------------------------------------------
// Launch
// ---------------------------------------------------------------------------
extern "C" void kernel_launch(void* const* d_in, const int* in_sizes, int n_in,
                              void* d_out, int out_size)
{
    const float* x  = (const float*)d_in[0];
    const float* W1 = (const float*)d_in[1];
    const float* b1 = (const float*)d_in[2];
    const float* W2 = (const float*)d_in[3];
    const float* b2 = (const float*)d_in[4];
    const float* W3 = (const float*)d_in[5];
    const float* b3 = (const float*)d_in[6];
    const float* u  = (const float*)d_in[7];
    float* out = (float*)d_out;

    float *h1, *h2;
    cudaGetSymbolAddress((void**)&h1, g_h1);
    cudaGetSymbolAddress((void**)&h2, g_h2);

    dim3 block(256);
    dim3 gridH(H_DIM / 128, M_ROWS / 128);           // (8, 256)
    dim3 gridO((O_DIM + 127) / 128, M_ROWS / 128);   // (8, 256)

    // h1 = elu(x @ W1 + b1)
    gemm_act_kernel<1><<<gridH, block>>>(x, W1, b1, h1, M_ROWS, H_DIM, 128);
    // h2 = sigmoid(h1 @ W2 + b2)
    gemm_act_kernel<2><<<gridH, block>>>(h1, W2, b2, h2, M_ROWS, H_DIM, H_DIM);
    // out = h2 @ W3 + b3   (raw logits)
    gemm_act_kernel<0><<<gridO, block>>>(h2, W3, b3, out, M_ROWS, O_DIM, H_DIM);
    // in-place segmented gumbel softmax
    gumbel_softmax_kernel<<<M_ROWS, block>>>(out, u);
}

// round 5
// speedup vs baseline: 2.3269x; 2.3269x over previous
#include <cuda_runtime.h>
#include <cuda_bf16.h>
#include <math.h>
#include <stdint.h>

#define M_ROWS 32768
#define H_DIM  1024
#define O_DIM  929
#define EPS_G  1e-20f

// ---------------------------------------------------------------------------
// Scratch (static device globals; no allocation allowed)
// ---------------------------------------------------------------------------
__device__ __align__(16) __nv_bfloat16 g_xh[(size_t)M_ROWS * 128];
__device__ __align__(16) __nv_bfloat16 g_xl[(size_t)M_ROWS * 128];
__device__ __align__(16) __nv_bfloat16 g_h1h[(size_t)M_ROWS * H_DIM];
__device__ __align__(16) __nv_bfloat16 g_h1l[(size_t)M_ROWS * H_DIM];
__device__ __align__(16) __nv_bfloat16 g_h2h[(size_t)M_ROWS * H_DIM];
__device__ __align__(16) __nv_bfloat16 g_h2l[(size_t)M_ROWS * H_DIM];
__device__ __align__(16) __nv_bfloat16 g_w1t_hi[1024 * 128];
__device__ __align__(16) __nv_bfloat16 g_w1t_lo[1024 * 128];
__device__ __align__(16) __nv_bfloat16 g_w2t_hi[1024 * 1024];
__device__ __align__(16) __nv_bfloat16 g_w2t_lo[1024 * 1024];
__device__ __align__(16) __nv_bfloat16 g_w3t_hi[1024 * 1024];
__device__ __align__(16) __nv_bfloat16 g_w3t_lo[1024 * 1024];

// ---------------------------------------------------------------------------
// PTX helpers (all target-portable: sm_80-era instructions)
// ---------------------------------------------------------------------------
static __device__ __forceinline__ uint32_t smem_to_u32(const void* p) {
    uint32_t a;
    asm("{ .reg .u64 t; cvta.to.shared.u64 t, %1; cvt.u32.u64 %0, t; }"
        : "=r"(a) : "l"(p));
    return a;
}

#define CP_ASYNC16(dst, src) \
    asm volatile("cp.async.cg.shared.global [%0], [%1], 16;" :: "r"(dst), "l"(src))
#define CP_COMMIT() asm volatile("cp.async.commit_group;")
#define CP_WAIT1()  asm volatile("cp.async.wait_group 1;")
#define CP_WAIT0()  asm volatile("cp.async.wait_group 0;")

#define LDMX4(r, a) \
    asm volatile("ldmatrix.sync.aligned.m8n8.x4.shared.b16 {%0,%1,%2,%3}, [%4];" \
        : "=r"((r)[0]), "=r"((r)[1]), "=r"((r)[2]), "=r"((r)[3]) : "r"(a))

static __device__ __forceinline__ void mma16816(float* c, const uint32_t* a,
                                                uint32_t b0, uint32_t b1) {
    asm volatile(
        "mma.sync.aligned.m16n8k16.row.col.f32.bf16.bf16.f32 "
        "{%0,%1,%2,%3}, {%4,%5,%6,%7}, {%8,%9}, {%0,%1,%2,%3};"
        : "+f"(c[0]), "+f"(c[1]), "+f"(c[2]), "+f"(c[3])
        : "r"(a[0]), "r"(a[1]), "r"(a[2]), "r"(a[3]), "r"(b0), "r"(b1));
}

#define SWZ(o) ((o) ^ ((((uint32_t)(o)) >> 3) & 0x70))

// ---------------------------------------------------------------------------
// x split: fp32 -> bf16 hi + bf16 lo
// ---------------------------------------------------------------------------
__global__ void split_x_kernel(const float* __restrict__ x,
                               __nv_bfloat16* __restrict__ xh,
                               __nv_bfloat16* __restrict__ xl, int n)
{
    const int i = blockIdx.x * blockDim.x + threadIdx.x;
    if (i < n) {
        const float v = x[i];
        const __nv_bfloat16 h = __float2bfloat16(v);
        xh[i] = h;
        xl[i] = __float2bfloat16(v - __bfloat162float(h));
    }
}

// ---------------------------------------------------------------------------
// Weight transpose + hi/lo split: W [K,N] fp32 -> Thi/Tlo [Npad,K] bf16
// (grid.x * 32 rows written; rows >= N zero-filled)
// ---------------------------------------------------------------------------
__global__ void transpose_split_kernel(const float* __restrict__ W, int K, int N,
                                       __nv_bfloat16* __restrict__ Thi,
                                       __nv_bfloat16* __restrict__ Tlo)
{
    __shared__ float t[32][33];
    const int n0 = blockIdx.x * 32, k0 = blockIdx.y * 32;
    const int tx = threadIdx.x, ty = threadIdx.y;
#pragma unroll
    for (int j = 0; j < 32; j += 8) {
        const int k = k0 + ty + j, n = n0 + tx;
        t[ty + j][tx] = (n < N) ? W[(size_t)k * N + n] : 0.f;
    }
    __syncthreads();
#pragma unroll
    for (int j = 0; j < 32; j += 8) {
        const int n = n0 + ty + j, k = k0 + tx;
        const float v = t[tx][ty + j];
        const __nv_bfloat16 h = __float2bfloat16(v);
        Thi[(size_t)n * K + k] = h;
        Tlo[(size_t)n * K + k] = __float2bfloat16(v - __bfloat162float(h));
    }
}

// ---------------------------------------------------------------------------
// Split-bf16 HMMA GEMM: C[M,Nlog] = act(A @ Bt^T + bias)
//   A   : hi/lo bf16 [M,K] row-major (K contig)
//   Bt  : hi/lo bf16 [Npad,K] (K contig), Npad = gridDim.x*128
// BM=BN=128, BK=64, 256 threads, 8 warps (4m x 2n), warp tile 32x64.
// Double-buffered cp.async, SW128-swizzled SMEM, ldmatrix + mma.m16n8k16.
// ACT: 0 none, 1 ELU, 2 sigmoid.  SPLIT_OUT: write bf16 hi/lo, else fp32.
// ---------------------------------------------------------------------------
#define GEMM_SMEM_BYTES (2 * 65536)

template <int ACT, bool SPLIT_OUT>
__global__ __launch_bounds__(256)
void gemm_mma(const __nv_bfloat16* __restrict__ Ah,
              const __nv_bfloat16* __restrict__ Al,
              const __nv_bfloat16* __restrict__ Bh,
              const __nv_bfloat16* __restrict__ Bl,
              const float* __restrict__ bias,
              float* __restrict__ Cf,
              __nv_bfloat16* __restrict__ Ch,
              __nv_bfloat16* __restrict__ Cl,
              int Nlog, int K)
{
    extern __shared__ char smem[];
    const uint32_t sm0 = smem_to_u32(smem);

    const int tid = threadIdx.x, wid = tid >> 5, lane = tid & 31;
    const int m0 = blockIdx.y * 128, n0 = blockIdx.x * 128;
    const int wm = (wid & 3) * 32;     // warp m offset in tile
    const int wn = (wid >> 2) * 64;    // warp n offset in tile

    const __nv_bfloat16* gAh = Ah + (size_t)m0 * K;
    const __nv_bfloat16* gAl = Al + (size_t)m0 * K;
    const __nv_bfloat16* gBh = Bh + (size_t)n0 * K;
    const __nv_bfloat16* gBl = Bl + (size_t)n0 * K;

    // cp.async mapping: per part, 1024 16B chunks; thread t covers ci = 4t..4t+3
    const int ci0  = tid << 2;

    auto load_stage = [&](int s, int buf) {
        const int k0 = s << 6;
        const uint32_t sb = sm0 + buf * 65536;
#pragma unroll
        for (int j = 0; j < 4; j++) {
            const int ci  = ci0 + j;
            const int row = ci >> 3, ch = ci & 7;
            const uint32_t dst = SWZ((uint32_t)(row * 128 + ch * 16));
            const size_t   go  = (size_t)row * K + k0 + ch * 8;
            CP_ASYNC16(sb + dst,         gAh + go);
            CP_ASYNC16(sb + 16384 + dst, gAl + go);
            CP_ASYNC16(sb + 32768 + dst, gBh + go);
            CP_ASYNC16(sb + 49152 + dst, gBl + go);
        }
        CP_COMMIT();
    };

    float c[16][4];
#pragma unroll
    for (int i = 0; i < 16; i++)
#pragma unroll
        for (int j = 0; j < 4; j++) c[i][j] = 0.f;

    const int nst = K >> 6;
    load_stage(0, 0);

    const int lrow = lane & 15;          // ldmatrix row within 16-row group
    const int lch  = (lane >> 4) << 4;   // 0 or 16 bytes (k sub-chunk)

    for (int s = 0; s < nst; s++) {
        if (s + 1 < nst) { load_stage(s + 1, (s + 1) & 1); CP_WAIT1(); }
        else             { CP_WAIT0(); }
        __syncthreads();

        const uint32_t sb = sm0 + (s & 1) * 65536;
#pragma unroll
        for (int kk = 0; kk < 4; kk++) {
            uint32_t ah[2][4], al[2][4], bh[4][4], bl[4][4];
#pragma unroll
            for (int am = 0; am < 2; am++) {
                const uint32_t o = SWZ((uint32_t)((wm + am * 16 + lrow) * 128 + kk * 32 + lch));
                LDMX4(ah[am], sb + o);
                LDMX4(al[am], sb + 16384 + o);
            }
#pragma unroll
            for (int g = 0; g < 4; g++) {
                const uint32_t o = SWZ((uint32_t)((wn + g * 16 + lrow) * 128 + kk * 32 + lch));
                LDMX4(bh[g], sb + 32768 + o);
                LDMX4(bl[g], sb + 49152 + o);
            }
#pragma unroll
            for (int am = 0; am < 2; am++)
#pragma unroll
                for (int nb = 0; nb < 8; nb++) {
                    const int g = nb >> 1, s2 = nb & 1;
                    float* cc = c[am * 8 + nb];
                    mma16816(cc, ah[am], bh[g][s2], bh[g][s2 + 2]);
                    mma16816(cc, al[am], bh[g][s2], bh[g][s2 + 2]);
                    mma16816(cc, ah[am], bl[g][s2], bl[g][s2 + 2]);
                }
        }
        __syncthreads();
    }

    // epilogue: bias + activation, write (hi/lo bf16) or fp32
    const int g  = lane >> 2;
    const int tg = (lane & 3) << 1;
#pragma unroll
    for (int am = 0; am < 2; am++) {
        const int rbase = m0 + wm + am * 16 + g;
#pragma unroll
        for (int nb = 0; nb < 8; nb++) {
            const int col = n0 + wn + nb * 8 + tg;
            float* cc = c[am * 8 + nb];
#pragma unroll
            for (int h = 0; h < 2; h++) {
                const int row = rbase + h * 8;
                float v0 = cc[h * 2 + 0];
                float v1 = cc[h * 2 + 1];
                if (SPLIT_OUT) {
                    v0 += bias[col];
                    v1 += bias[col + 1];
                    if (ACT == 1) {
                        v0 = (v0 > 0.f) ? v0 : expm1f(v0);
                        v1 = (v1 > 0.f) ? v1 : expm1f(v1);
                    } else if (ACT == 2) {
                        v0 = 1.f / (1.f + __expf(-v0));
                        v1 = 1.f / (1.f + __expf(-v1));
                    }
                    const __nv_bfloat16 h0 = __float2bfloat16(v0);
                    const __nv_bfloat16 h1 = __float2bfloat16(v1);
                    const __nv_bfloat16 l0 = __float2bfloat16(v0 - __bfloat162float(h0));
                    const __nv_bfloat16 l1 = __float2bfloat16(v1 - __bfloat162float(h1));
                    const size_t off = (size_t)row * Nlog + col;
                    *(__nv_bfloat162*)(Ch + off) = __halves2bfloat162(h0, h1);
                    *(__nv_bfloat162*)(Cl + off) = __halves2bfloat162(l0, l1);
                } else {
                    const size_t off = (size_t)row * Nlog + col;
                    if (col < Nlog)     Cf[off]     = v0 + bias[col];
                    if (col + 1 < Nlog) Cf[off + 1] = v1 + bias[col + 1];
                }
            }
        }
    }
}

// ---------------------------------------------------------------------------
// Gumbel softmax: one 288-thread block (9 warps) per row.
// Big segment (off=205, n=711): block-cooperative (2 block reductions).
// 9 small segments: one warp each, shfl-only reductions.
// ---------------------------------------------------------------------------
__constant__ int c_soff[9] = {0, 29, 32, 38, 45, 105, 129, 916, 919};
__constant__ int c_snum[9] = {29, 2, 6, 7, 59, 24, 76, 3, 9};

__global__ __launch_bounds__(288)
void gumbel_softmax2(float* __restrict__ out, const float* __restrict__ u)
{
    const int row = blockIdx.x, tid = threadIdx.x, wid = tid >> 5, lane = tid & 31;
    float* orow = out + (size_t)row * O_DIM;
    const float* urow = u + (size_t)row * O_DIM;
    __shared__ float red[16];
    __shared__ float bval;

    // ---- big segment: off=205, n=711 ----
    float y[3];
    float lmax = -3.4e38f;
#pragma unroll
    for (int it = 0; it < 3; it++) {
        const int i = tid + it * 288;
        if (i < 711) {
            const float uu = urow[205 + i];
            const float gg = -logf(-logf(uu + EPS_G) + EPS_G);
            const float v = (orow[205 + i] + gg) * 1.25f;
            y[it] = v;
            lmax = fmaxf(lmax, v);
        } else y[it] = -3.4e38f;
    }
#pragma unroll
    for (int o = 16; o > 0; o >>= 1) lmax = fmaxf(lmax, __shfl_xor_sync(~0u, lmax, o));
    if (lane == 0) red[wid] = lmax;
    __syncthreads();
    if (tid < 32) {
        float w = (lane < 9) ? red[lane] : -3.4e38f;
#pragma unroll
        for (int o = 8; o > 0; o >>= 1) w = fmaxf(w, __shfl_xor_sync(~0u, w, o));
        if (lane == 0) bval = w;
    }
    __syncthreads();
    const float m = bval;
    float lsum = 0.f;
#pragma unroll
    for (int it = 0; it < 3; it++) {
        const int i = tid + it * 288;
        if (i < 711) { const float e = __expf(y[it] - m); y[it] = e; lsum += e; }
    }
#pragma unroll
    for (int o = 16; o > 0; o >>= 1) lsum += __shfl_xor_sync(~0u, lsum, o);
    if (lane == 0) red[wid] = lsum;
    __syncthreads();
    if (tid < 32) {
        float w = (lane < 9) ? red[lane] : 0.f;
#pragma unroll
        for (int o = 8; o > 0; o >>= 1) w += __shfl_xor_sync(~0u, w, o);
        if (lane == 0) bval = w;
    }
    __syncthreads();
    const float inv = 1.f / bval;
#pragma unroll
    for (int it = 0; it < 3; it++) {
        const int i = tid + it * 288;
        if (i < 711) orow[205 + i] = y[it] * inv;
    }

    // ---- small segments: warp `wid` handles segment `wid` ----
    {
        const int off = c_soff[wid], n = c_snum[wid];
        float z[3];
        float wmax = -3.4e38f;
#pragma unroll
        for (int it = 0; it < 3; it++) {
            const int i = lane + it * 32;
            if (i < n) {
                const float uu = urow[off + i];
                const float gg = -logf(-logf(uu + EPS_G) + EPS_G);
                const float v = (orow[off + i] + gg) * 1.25f;
                z[it] = v;
                wmax = fmaxf(wmax, v);
            } else z[it] = -3.4e38f;
        }
#pragma unroll
        for (int o = 16; o > 0; o >>= 1) wmax = fmaxf(wmax, __shfl_xor_sync(~0u, wmax, o));
        float wsum = 0.f;
#pragma unroll
        for (int it = 0; it < 3; it++) {
            const int i = lane + it * 32;
            if (i < n) { const float e = __expf(z[it] - wmax); z[it] = e; wsum += e; }
        }
#pragma unroll
        for (int o = 16; o > 0; o >>= 1) wsum += __shfl_xor_sync(~0u, wsum, o);
        const float winv = 1.f / wsum;
#pragma unroll
        for (int it = 0; it < 3; it++) {
            const int i = lane + it * 32;
            if (i < n) orow[off + i] = z[it] * winv;
        }
    }
}

// ---------------------------------------------------------------------------
// Launch
// ---------------------------------------------------------------------------
extern "C" void kernel_launch(void* const* d_in, const int* in_sizes, int n_in,
                              void* d_out, int out_size)
{
    const float* x  = (const float*)d_in[0];
    const float* W1 = (const float*)d_in[1];
    const float* b1 = (const float*)d_in[2];
    const float* W2 = (const float*)d_in[3];
    const float* b2 = (const float*)d_in[4];
    const float* W3 = (const float*)d_in[5];
    const float* b3 = (const float*)d_in[6];
    const float* u  = (const float*)d_in[7];
    float* out = (float*)d_out;

    __nv_bfloat16 *xh, *xl, *h1h, *h1l, *h2h, *h2l;
    __nv_bfloat16 *w1h, *w1l, *w2h, *w2l, *w3h, *w3l;
    cudaGetSymbolAddress((void**)&xh,  g_xh);
    cudaGetSymbolAddress((void**)&xl,  g_xl);
    cudaGetSymbolAddress((void**)&h1h, g_h1h);
    cudaGetSymbolAddress((void**)&h1l, g_h1l);
    cudaGetSymbolAddress((void**)&h2h, g_h2h);
    cudaGetSymbolAddress((void**)&h2l, g_h2l);
    cudaGetSymbolAddress((void**)&w1h, g_w1t_hi);
    cudaGetSymbolAddress((void**)&w1l, g_w1t_lo);
    cudaGetSymbolAddress((void**)&w2h, g_w2t_hi);
    cudaGetSymbolAddress((void**)&w2l, g_w2t_lo);
    cudaGetSymbolAddress((void**)&w3h, g_w3t_hi);
    cudaGetSymbolAddress((void**)&w3l, g_w3t_lo);

    cudaFuncSetAttribute(gemm_mma<1, true>,  cudaFuncAttributeMaxDynamicSharedMemorySize, GEMM_SMEM_BYTES);
    cudaFuncSetAttribute(gemm_mma<2, true>,  cudaFuncAttributeMaxDynamicSharedMemorySize, GEMM_SMEM_BYTES);
    cudaFuncSetAttribute(gemm_mma<0, false>, cudaFuncAttributeMaxDynamicSharedMemorySize, GEMM_SMEM_BYTES);

    // input / weight preparation
    split_x_kernel<<<(M_ROWS * 128 + 255) / 256, 256>>>(x, xh, xl, M_ROWS * 128);
    dim3 tsb(32, 8);
    transpose_split_kernel<<<dim3(32, 4),  tsb>>>(W1, 128,  1024, w1h, w1l);
    transpose_split_kernel<<<dim3(32, 32), tsb>>>(W2, 1024, 1024, w2h, w2l);
    transpose_split_kernel<<<dim3(32, 32), tsb>>>(W3, 1024, 929,  w3h, w3l);

    dim3 grid(8, 256), block(256);
    // h1 = elu(x @ W1 + b1), stored split
    gemm_mma<1, true><<<grid, block, GEMM_SMEM_BYTES>>>(
        xh, xl, w1h, w1l, b1, nullptr, h1h, h1l, H_DIM, 128);
    // h2 = sigmoid(h1 @ W2 + b2), stored split
    gemm_mma<2, true><<<grid, block, GEMM_SMEM_BYTES>>>(
        h1h, h1l, w2h, w2l, b2, nullptr, h2h, h2l, H_DIM, H_DIM);
    // logits = h2 @ W3 + b3, fp32 to d_out
    gemm_mma<0, false><<<grid, block, GEMM_SMEM_BYTES>>>(
        h2h, h2l, w3h, w3l, b3, out, nullptr, nullptr, O_DIM, H_DIM);
    // segmented gumbel softmax in place
    gumbel_softmax2<<<M_ROWS, 288>>>(out, u);
}

// round 9
// speedup vs baseline: 5.3738x; 2.3094x over previous
#include <cuda_runtime.h>
#include <cuda_fp16.h>
#include <math.h>
#include <stdint.h>

#define M_ROWS 32768
#define H_DIM  1024
#define O_DIM  929
#define EPS_G  1e-20f

// ---------------------------------------------------------------------------
// Scratch (static device globals; no allocation allowed)
// ---------------------------------------------------------------------------
__device__ __align__(16) __half g_x16[(size_t)M_ROWS * 128];
__device__ __align__(16) __half g_h1[(size_t)M_ROWS * H_DIM];
__device__ __align__(16) __half g_h2[(size_t)M_ROWS * H_DIM];
__device__ __align__(16) __half g_w1t[1024 * 128];
__device__ __align__(16) __half g_w2t[1024 * 1024];
__device__ __align__(16) __half g_w3t[1024 * 1024];

// ---------------------------------------------------------------------------
// PTX helpers (sm_80-era, target-portable)
// ---------------------------------------------------------------------------
static __device__ __forceinline__ uint32_t smem_to_u32(const void* p) {
    uint32_t a;
    asm("{ .reg .u64 t; cvta.to.shared.u64 t, %1; cvt.u32.u64 %0, t; }"
        : "=r"(a) : "l"(p));
    return a;
}

#define CP_ASYNC16(dst, src) \
    asm volatile("cp.async.cg.shared.global [%0], [%1], 16;" :: "r"(dst), "l"(src))
#define CP_COMMIT() asm volatile("cp.async.commit_group;")
#define CP_WAIT1()  asm volatile("cp.async.wait_group 1;")
#define CP_WAIT0()  asm volatile("cp.async.wait_group 0;")

#define LDMX4(r, a) \
    asm volatile("ldmatrix.sync.aligned.m8n8.x4.shared.b16 {%0,%1,%2,%3}, [%4];" \
        : "=r"((r)[0]), "=r"((r)[1]), "=r"((r)[2]), "=r"((r)[3]) : "r"(a))

static __device__ __forceinline__ void mma16816(float* c, const uint32_t* a,
                                                uint32_t b0, uint32_t b1) {
    asm volatile(
        "mma.sync.aligned.m16n8k16.row.col.f32.f16.f16.f32 "
        "{%0,%1,%2,%3}, {%4,%5,%6,%7}, {%8,%9}, {%0,%1,%2,%3};"
        : "+f"(c[0]), "+f"(c[1]), "+f"(c[2]), "+f"(c[3])
        : "r"(a[0]), "r"(a[1]), "r"(a[2]), "r"(a[3]), "r"(b0), "r"(b1));
}

#define SWZ(o) ((o) ^ ((((uint32_t)(o)) >> 3) & 0x70))

// ---------------------------------------------------------------------------
// x convert: fp32 -> fp16
// ---------------------------------------------------------------------------
__global__ void convert_x_kernel(const float* __restrict__ x,
                                 __half* __restrict__ x16, int n)
{
    const int i = blockIdx.x * blockDim.x + threadIdx.x;
    if (i < n) x16[i] = __float2half(x[i]);
}

// ---------------------------------------------------------------------------
// Weight transpose: W [K,N] fp32 -> T [Npad,K] fp16 (rows >= N zero-filled)
// ---------------------------------------------------------------------------
__global__ void transpose_h_kernel(const float* __restrict__ W, int K, int N,
                                   __half* __restrict__ T)
{
    __shared__ float t[32][33];
    const int n0 = blockIdx.x * 32, k0 = blockIdx.y * 32;
    const int tx = threadIdx.x, ty = threadIdx.y;
#pragma unroll
    for (int j = 0; j < 32; j += 8) {
        const int k = k0 + ty + j, n = n0 + tx;
        t[ty + j][tx] = (n < N) ? W[(size_t)k * N + n] : 0.f;
    }
    __syncthreads();
#pragma unroll
    for (int j = 0; j < 32; j += 8) {
        const int n = n0 + ty + j, k = k0 + tx;
        T[(size_t)n * K + k] = __float2half(t[tx][ty + j]);
    }
}

// ---------------------------------------------------------------------------
// fp16 HMMA GEMM: C[M,Nlog] = act(A @ Bt^T + bias)
//   A  : fp16 [M,K] row-major (K contig)
//   Bt : fp16 [Npad,K] (K contig), Npad = gridDim.x*128
// BM=BN=128, BK=64, 256 threads, 8 warps (4m x 2n), warp tile 32x64.
// Double-buffered cp.async, SW128 swizzle, ldmatrix + mma.m16n8k16.f16.
// ACT: 0 none, 1 ELU, 2 sigmoid.  HALF_OUT: write fp16, else fp32.
// ---------------------------------------------------------------------------
#define STAGE_BYTES 32768
#define GEMM_SMEM_BYTES (2 * STAGE_BYTES)

template <int ACT, bool HALF_OUT>
__global__ __launch_bounds__(256)
void gemm_mma(const __half* __restrict__ A,
              const __half* __restrict__ B,
              const float* __restrict__ bias,
              float* __restrict__ Cf,
              __half* __restrict__ Ch,
              int Nlog, int K)
{
    extern __shared__ char smem[];
    const uint32_t sm0 = smem_to_u32(smem);

    const int tid = threadIdx.x, wid = tid >> 5, lane = tid & 31;
    const int m0 = blockIdx.y * 128, n0 = blockIdx.x * 128;
    const int wm = (wid & 3) * 32;     // warp m offset in tile
    const int wn = (wid >> 2) * 64;    // warp n offset in tile

    const __half* gA = A + (size_t)m0 * K;
    const __half* gB = B + (size_t)n0 * K;

    // 1024 16B chunks per operand part; thread t covers ci = 4t..4t+3
    const int ci0 = tid << 2;

    auto load_stage = [&](int s, int buf) {
        const int k0 = s << 6;
        const uint32_t sb = sm0 + buf * STAGE_BYTES;
#pragma unroll
        for (int j = 0; j < 4; j++) {
            const int ci  = ci0 + j;
            const int row = ci >> 3, ch = ci & 7;
            const uint32_t dst = SWZ((uint32_t)(row * 128 + ch * 16));
            const size_t   go  = (size_t)row * K + k0 + ch * 8;
            CP_ASYNC16(sb + dst,         gA + go);
            CP_ASYNC16(sb + 16384 + dst, gB + go);
        }
        CP_COMMIT();
    };

    float c[16][4];
#pragma unroll
    for (int i = 0; i < 16; i++)
#pragma unroll
        for (int j = 0; j < 4; j++) c[i][j] = 0.f;

    const int nst = K >> 6;
    load_stage(0, 0);

    const int lrow = lane & 15;          // ldmatrix row within 16-row group
    const int lch  = (lane >> 4) << 4;   // 0 or 16 bytes (k sub-chunk)

    for (int s = 0; s < nst; s++) {
        if (s + 1 < nst) { load_stage(s + 1, (s + 1) & 1); CP_WAIT1(); }
        else             { CP_WAIT0(); }
        __syncthreads();

        const uint32_t sb = sm0 + (s & 1) * STAGE_BYTES;
#pragma unroll
        for (int kk = 0; kk < 4; kk++) {
            uint32_t a[2][4], b[4][4];
#pragma unroll
            for (int am = 0; am < 2; am++) {
                const uint32_t o = SWZ((uint32_t)((wm + am * 16 + lrow) * 128 + kk * 32 + lch));
                LDMX4(a[am], sb + o);
            }
#pragma unroll
            for (int g = 0; g < 4; g++) {
                const uint32_t o = SWZ((uint32_t)((wn + g * 16 + lrow) * 128 + kk * 32 + lch));
                LDMX4(b[g], sb + 16384 + o);
            }
#pragma unroll
            for (int am = 0; am < 2; am++)
#pragma unroll
                for (int nb = 0; nb < 8; nb++) {
                    const int g = nb >> 1, s2 = nb & 1;
                    mma16816(c[am * 8 + nb], a[am], b[g][s2], b[g][s2 + 2]);
                }
        }
        __syncthreads();
    }

    // epilogue: bias + activation
    const int g  = lane >> 2;
    const int tg = (lane & 3) << 1;
#pragma unroll
    for (int am = 0; am < 2; am++) {
        const int rbase = m0 + wm + am * 16 + g;
#pragma unroll
        for (int nb = 0; nb < 8; nb++) {
            const int col = n0 + wn + nb * 8 + tg;
            float* cc = c[am * 8 + nb];
#pragma unroll
            for (int h = 0; h < 2; h++) {
                const int row = rbase + h * 8;
                float v0 = cc[h * 2 + 0] + bias[col];
                float v1 = cc[h * 2 + 1] + bias[col + 1];
                if (ACT == 1) {
                    v0 = (v0 > 0.f) ? v0 : expm1f(v0);
                    v1 = (v1 > 0.f) ? v1 : expm1f(v1);
                } else if (ACT == 2) {
                    v0 = 1.f / (1.f + __expf(-v0));
                    v1 = 1.f / (1.f + __expf(-v1));
                }
                if (HALF_OUT) {
                    const size_t off = (size_t)row * Nlog + col;
                    *(__half2*)(Ch + off) = __floats2half2_rn(v0, v1);
                } else {
                    const size_t off = (size_t)row * Nlog + col;
                    if (col < Nlog)     Cf[off]     = v0;
                    if (col + 1 < Nlog) Cf[off + 1] = v1;
                }
            }
        }
    }
}

// ---------------------------------------------------------------------------
// Gumbel softmax: one 288-thread block (9 warps) per row.
// Big segment (off=205, n=711): block-cooperative (2 block reductions).
// 9 small segments: one warp each, shfl-only reductions.
// ---------------------------------------------------------------------------
__constant__ int c_soff[9] = {0, 29, 32, 38, 45, 105, 129, 916, 919};
__constant__ int c_snum[9] = {29, 2, 6, 7, 59, 24, 76, 3, 9};

__global__ __launch_bounds__(288)
void gumbel_softmax2(float* __restrict__ out, const float* __restrict__ u)
{
    const int row = blockIdx.x, tid = threadIdx.x, wid = tid >> 5, lane = tid & 31;
    float* orow = out + (size_t)row * O_DIM;
    const float* urow = u + (size_t)row * O_DIM;
    __shared__ float red[16];
    __shared__ float bval;

    // ---- big segment: off=205, n=711 ----
    float y[3];
    float lmax = -3.4e38f;
#pragma unroll
    for (int it = 0; it < 3; it++) {
        const int i = tid + it * 288;
        if (i < 711) {
            const float uu = urow[205 + i];
            const float gg = -logf(-logf(uu + EPS_G) + EPS_G);
            const float v = (orow[205 + i] + gg) * 1.25f;
            y[it] = v;
            lmax = fmaxf(lmax, v);
        } else y[it] = -3.4e38f;
    }
#pragma unroll
    for (int o = 16; o > 0; o >>= 1) lmax = fmaxf(lmax, __shfl_xor_sync(~0u, lmax, o));
    if (lane == 0) red[wid] = lmax;
    __syncthreads();
    if (tid < 32) {
        float w = (lane < 9) ? red[lane] : -3.4e38f;
#pragma unroll
        for (int o = 8; o > 0; o >>= 1) w = fmaxf(w, __shfl_xor_sync(~0u, w, o));
        if (lane == 0) bval = w;
    }
    __syncthreads();
    const float m = bval;
    float lsum = 0.f;
#pragma unroll
    for (int it = 0; it < 3; it++) {
        const int i = tid + it * 288;
        if (i < 711) { const float e = __expf(y[it] - m); y[it] = e; lsum += e; }
    }
#pragma unroll
    for (int o = 16; o > 0; o >>= 1) lsum += __shfl_xor_sync(~0u, lsum, o);
    if (lane == 0) red[wid] = lsum;
    __syncthreads();
    if (tid < 32) {
        float w = (lane < 9) ? red[lane] : 0.f;
#pragma unroll
        for (int o = 8; o > 0; o >>= 1) w += __shfl_xor_sync(~0u, w, o);
        if (lane == 0) bval = w;
    }
    __syncthreads();
    const float inv = 1.f / bval;
#pragma unroll
    for (int it = 0; it < 3; it++) {
        const int i = tid + it * 288;
        if (i < 711) orow[205 + i] = y[it] * inv;
    }

    // ---- small segments: warp `wid` handles segment `wid` ----
    {
        const int off = c_soff[wid], n = c_snum[wid];
        float z[3];
        float wmax = -3.4e38f;
#pragma unroll
        for (int it = 0; it < 3; it++) {
            const int i = lane + it * 32;
            if (i < n) {
                const float uu = urow[off + i];
                const float gg = -logf(-logf(uu + EPS_G) + EPS_G);
                const float v = (orow[off + i] + gg) * 1.25f;
                z[it] = v;
                wmax = fmaxf(wmax, v);
            } else z[it] = -3.4e38f;
        }
#pragma unroll
        for (int o = 16; o > 0; o >>= 1) wmax = fmaxf(wmax, __shfl_xor_sync(~0u, wmax, o));
        float wsum = 0.f;
#pragma unroll
        for (int it = 0; it < 3; it++) {
            const int i = lane + it * 32;
            if (i < n) { const float e = __expf(z[it] - wmax); z[it] = e; wsum += e; }
        }
#pragma unroll
        for (int o = 16; o > 0; o >>= 1) wsum += __shfl_xor_sync(~0u, wsum, o);
        const float winv = 1.f / wsum;
#pragma unroll
        for (int it = 0; it < 3; it++) {
            const int i = lane + it * 32;
            if (i < n) orow[off + i] = z[it] * winv;
        }
    }
}

// ---------------------------------------------------------------------------
// Launch
// ---------------------------------------------------------------------------
extern "C" void kernel_launch(void* const* d_in, const int* in_sizes, int n_in,
                              void* d_out, int out_size)
{
    const float* x  = (const float*)d_in[0];
    const float* W1 = (const float*)d_in[1];
    const float* b1 = (const float*)d_in[2];
    const float* W2 = (const float*)d_in[3];
    const float* b2 = (const float*)d_in[4];
    const float* W3 = (const float*)d_in[5];
    const float* b3 = (const float*)d_in[6];
    const float* u  = (const float*)d_in[7];
    float* out = (float*)d_out;

    __half *x16, *h1, *h2, *w1t, *w2t, *w3t;
    cudaGetSymbolAddress((void**)&x16, g_x16);
    cudaGetSymbolAddress((void**)&h1,  g_h1);
    cudaGetSymbolAddress((void**)&h2,  g_h2);
    cudaGetSymbolAddress((void**)&w1t, g_w1t);
    cudaGetSymbolAddress((void**)&w2t, g_w2t);
    cudaGetSymbolAddress((void**)&w3t, g_w3t);

    cudaFuncSetAttribute(gemm_mma<1, true>,  cudaFuncAttributeMaxDynamicSharedMemorySize, GEMM_SMEM_BYTES);
    cudaFuncSetAttribute(gemm_mma<2, true>,  cudaFuncAttributeMaxDynamicSharedMemorySize, GEMM_SMEM_BYTES);
    cudaFuncSetAttribute(gemm_mma<0, false>, cudaFuncAttributeMaxDynamicSharedMemorySize, GEMM_SMEM_BYTES);

    // input / weight preparation
    convert_x_kernel<<<(M_ROWS * 128 + 255) / 256, 256>>>(x, x16, M_ROWS * 128);
    dim3 tsb(32, 8);
    transpose_h_kernel<<<dim3(32, 4),  tsb>>>(W1, 128,  1024, w1t);
    transpose_h_kernel<<<dim3(32, 32), tsb>>>(W2, 1024, 1024, w2t);
    transpose_h_kernel<<<dim3(32, 32), tsb>>>(W3, 1024, 929,  w3t);

    dim3 grid(8, 256), block(256);
    // h1 = elu(x @ W1 + b1), fp16
    gemm_mma<1, true><<<grid, block, GEMM_SMEM_BYTES>>>(
        x16, w1t, b1, nullptr, h1, H_DIM, 128);
    // h2 = sigmoid(h1 @ W2 + b2), fp16
    gemm_mma<2, true><<<grid, block, GEMM_SMEM_BYTES>>>(
        h1, w2t, b2, nullptr, h2, H_DIM, H_DIM);
    // logits = h2 @ W3 + b3, fp32 to d_out
    gemm_mma<0, false><<<grid, block, GEMM_SMEM_BYTES>>>(
        h2, w3t, b3, out, nullptr, O_DIM, H_DIM);
    // segmented gumbel softmax in place
    gumbel_softmax2<<<M_ROWS, 288>>>(out, u);
}

// round 10
// speedup vs baseline: 5.6316x; 1.0480x over previous
#include <cuda_runtime.h>
#include <cuda_fp16.h>
#include <math.h>
#include <stdint.h>

#define M_ROWS 32768
#define H_DIM  1024
#define O_DIM  929
#define EPS_G  1e-20f

// ---------------------------------------------------------------------------
// Scratch (static device globals; no allocation allowed)
// ---------------------------------------------------------------------------
__device__ __align__(16) __half g_x16[(size_t)M_ROWS * 128];
__device__ __align__(16) __half g_h1[(size_t)M_ROWS * H_DIM];
__device__ __align__(16) __half g_h2[(size_t)M_ROWS * H_DIM];
__device__ __align__(16) __half g_w1t[1024 * 128];
__device__ __align__(16) __half g_w2t[1024 * 1024];
__device__ __align__(16) __half g_w3t[1024 * 1024];

// ---------------------------------------------------------------------------
// PTX helpers (sm_80-era, target-portable)
// ---------------------------------------------------------------------------
static __device__ __forceinline__ uint32_t smem_to_u32(const void* p) {
    uint32_t a;
    asm("{ .reg .u64 t; cvta.to.shared.u64 t, %1; cvt.u32.u64 %0, t; }"
        : "=r"(a) : "l"(p));
    return a;
}

#define CP_ASYNC16(dst, src) \
    asm volatile("cp.async.cg.shared.global [%0], [%1], 16;" :: "r"(dst), "l"(src))
#define CP_COMMIT() asm volatile("cp.async.commit_group;")
#define CP_WAIT1()  asm volatile("cp.async.wait_group 1;")
#define CP_WAIT0()  asm volatile("cp.async.wait_group 0;")

#define LDMX4(r, a) \
    asm volatile("ldmatrix.sync.aligned.m8n8.x4.shared.b16 {%0,%1,%2,%3}, [%4];" \
        : "=r"((r)[0]), "=r"((r)[1]), "=r"((r)[2]), "=r"((r)[3]) : "r"(a))

static __device__ __forceinline__ void mma16816(float* c, const uint32_t* a,
                                                uint32_t b0, uint32_t b1) {
    asm volatile(
        "mma.sync.aligned.m16n8k16.row.col.f32.f16.f16.f32 "
        "{%0,%1,%2,%3}, {%4,%5,%6,%7}, {%8,%9}, {%0,%1,%2,%3};"
        : "+f"(c[0]), "+f"(c[1]), "+f"(c[2]), "+f"(c[3])
        : "r"(a[0]), "r"(a[1]), "r"(a[2]), "r"(a[3]), "r"(b0), "r"(b1));
}

#define SWZ(o) ((o) ^ ((((uint32_t)(o)) >> 3) & 0x70))

// ---------------------------------------------------------------------------
// x convert: fp32 -> fp16
// ---------------------------------------------------------------------------
__global__ void convert_x_kernel(const float* __restrict__ x,
                                 __half* __restrict__ x16, int n)
{
    const int i = blockIdx.x * blockDim.x + threadIdx.x;
    if (i < n) x16[i] = __float2half(x[i]);
}

// ---------------------------------------------------------------------------
// Weight transpose: W [K,N] fp32 -> T [Npad,K] fp16 (rows >= N zero-filled)
// ---------------------------------------------------------------------------
__global__ void transpose_h_kernel(const float* __restrict__ W, int K, int N,
                                   __half* __restrict__ T)
{
    __shared__ float t[32][33];
    const int n0 = blockIdx.x * 32, k0 = blockIdx.y * 32;
    const int tx = threadIdx.x, ty = threadIdx.y;
#pragma unroll
    for (int j = 0; j < 32; j += 8) {
        const int k = k0 + ty + j, n = n0 + tx;
        t[ty + j][tx] = (n < N) ? W[(size_t)k * N + n] : 0.f;
    }
    __syncthreads();
#pragma unroll
    for (int j = 0; j < 32; j += 8) {
        const int n = n0 + ty + j, k = k0 + tx;
        T[(size_t)n * K + k] = __float2half(t[tx][ty + j]);
    }
}

// ---------------------------------------------------------------------------
// fp16 HMMA GEMM: C[M,Nlog] = act(A @ Bt^T + bias)
//   A  : fp16 [M,K] row-major (K contig)
//   Bt : fp16 [Npad,K] (K contig), Npad = gridDim.x*128
// BM=BN=128, BK=64, 256 threads, 8 warps (4m x 2n), warp tile 32x64.
// Triple-buffered cp.async, ONE barrier per stage, SW128 swizzle,
// ldmatrix + mma.m16n8k16.f16.
// ACT: 0 none, 1 ELU, 2 sigmoid.  HALF_OUT: write fp16, else fp32.
// ---------------------------------------------------------------------------
#define STAGE_BYTES 32768
#define GEMM_SMEM_BYTES (3 * STAGE_BYTES)

template <int ACT, bool HALF_OUT>
__global__ __launch_bounds__(256)
void gemm_mma(const __half* __restrict__ A,
              const __half* __restrict__ B,
              const float* __restrict__ bias,
              float* __restrict__ Cf,
              __half* __restrict__ Ch,
              int Nlog, int K)
{
    extern __shared__ char smem[];
    const uint32_t sm0 = smem_to_u32(smem);

    const int tid = threadIdx.x, wid = tid >> 5, lane = tid & 31;
    const int m0 = blockIdx.y * 128, n0 = blockIdx.x * 128;
    const int wm = (wid & 3) * 32;     // warp m offset in tile
    const int wn = (wid >> 2) * 64;    // warp n offset in tile

    const __half* gA = A + (size_t)m0 * K;
    const __half* gB = B + (size_t)n0 * K;

    // 1024 16B chunks per operand part; thread t covers ci = 4t..4t+3
    const int ci0 = tid << 2;

    auto load_stage = [&](int s, int buf) {
        const int k0 = s << 6;
        const uint32_t sb = sm0 + buf * STAGE_BYTES;
#pragma unroll
        for (int j = 0; j < 4; j++) {
            const int ci  = ci0 + j;
            const int row = ci >> 3, ch = ci & 7;
            const uint32_t dst = SWZ((uint32_t)(row * 128 + ch * 16));
            const size_t   go  = (size_t)row * K + k0 + ch * 8;
            CP_ASYNC16(sb + dst,         gA + go);
            CP_ASYNC16(sb + 16384 + dst, gB + go);
        }
        CP_COMMIT();
    };

    float c[16][4];
#pragma unroll
    for (int i = 0; i < 16; i++)
#pragma unroll
        for (int j = 0; j < 4; j++) c[i][j] = 0.f;

    const int nst = K >> 6;
    // prologue: stages 0 and 1 in flight
    load_stage(0, 0);
    if (nst > 1) load_stage(1, 1);

    const int lrow = lane & 15;          // ldmatrix row within 16-row group
    const int lch  = (lane >> 4) << 4;   // 0 or 16 bytes (k sub-chunk)

    int buf = 0;                          // buf = s % 3
    for (int s = 0; s < nst; s++) {
        // stage s must be complete:
        if (s + 1 < nst) { CP_WAIT1(); }
        else             { CP_WAIT0(); }
        __syncthreads();   // ALSO releases buffer (s+2)%3 (= (s-1)%3) for reuse

        // issue stage s+2 into buffer (s+2)%3 — safe after the barrier
        if (s + 2 < nst) {
            int nb = buf + 2; if (nb >= 3) nb -= 3;
            load_stage(s + 2, nb);
        }

        const uint32_t sb = sm0 + buf * STAGE_BYTES;
#pragma unroll
        for (int kk = 0; kk < 4; kk++) {
            uint32_t a[2][4], b[4][4];
#pragma unroll
            for (int am = 0; am < 2; am++) {
                const uint32_t o = SWZ((uint32_t)((wm + am * 16 + lrow) * 128 + kk * 32 + lch));
                LDMX4(a[am], sb + o);
            }
#pragma unroll
            for (int g = 0; g < 4; g++) {
                const uint32_t o = SWZ((uint32_t)((wn + g * 16 + lrow) * 128 + kk * 32 + lch));
                LDMX4(b[g], sb + 16384 + o);
            }
#pragma unroll
            for (int am = 0; am < 2; am++)
#pragma unroll
                for (int nb2 = 0; nb2 < 8; nb2++) {
                    const int g = nb2 >> 1, s2 = nb2 & 1;
                    mma16816(c[am * 8 + nb2], a[am], b[g][s2], b[g][s2 + 2]);
                }
        }
        if (++buf == 3) buf = 0;
    }

    // epilogue: bias + activation
    const int g  = lane >> 2;
    const int tg = (lane & 3) << 1;
#pragma unroll
    for (int am = 0; am < 2; am++) {
        const int rbase = m0 + wm + am * 16 + g;
#pragma unroll
        for (int nb = 0; nb < 8; nb++) {
            const int col = n0 + wn + nb * 8 + tg;
            float* cc = c[am * 8 + nb];
#pragma unroll
            for (int h = 0; h < 2; h++) {
                const int row = rbase + h * 8;
                float v0 = cc[h * 2 + 0] + bias[col];
                float v1 = cc[h * 2 + 1] + bias[col + 1];
                if (ACT == 1) {
                    v0 = (v0 > 0.f) ? v0 : (__expf(v0) - 1.f);
                    v1 = (v1 > 0.f) ? v1 : (__expf(v1) - 1.f);
                } else if (ACT == 2) {
                    v0 = 1.f / (1.f + __expf(-v0));
                    v1 = 1.f / (1.f + __expf(-v1));
                }
                if (HALF_OUT) {
                    const size_t off = (size_t)row * Nlog + col;
                    *(__half2*)(Ch + off) = __floats2half2_rn(v0, v1);
                } else {
                    const size_t off = (size_t)row * Nlog + col;
                    if (col < Nlog)     Cf[off]     = v0;
                    if (col + 1 < Nlog) Cf[off + 1] = v1;
                }
            }
        }
    }
}

// ---------------------------------------------------------------------------
// Gumbel helper: g = -log(-log(u + eps) + eps)
// Inner log: MUFU fast path unless u > 0.99 (where |ln u| -> 0 makes MUFU's
// absolute error blow up relatively); outer log: always MUFU (abs err ~1.6e-7).
// ---------------------------------------------------------------------------
static __device__ __forceinline__ float gumbel_g(float u)
{
    const float up = u + EPS_G;
    float t;
    if (up <= 0.99f) t = -__logf(up);
    else             t = -logf(up);
    return -__logf(t + EPS_G);
}

// ---------------------------------------------------------------------------
// Gumbel softmax: one 288-thread block (9 warps) per row.
// Big segment (off=205, n=711): block-cooperative (2 block reductions).
// 9 small segments: one warp each, shfl-only reductions.
// ---------------------------------------------------------------------------
__constant__ int c_soff[9] = {0, 29, 32, 38, 45, 105, 129, 916, 919};
__constant__ int c_snum[9] = {29, 2, 6, 7, 59, 24, 76, 3, 9};

__global__ __launch_bounds__(288)
void gumbel_softmax2(float* __restrict__ out, const float* __restrict__ u)
{
    const int row = blockIdx.x, tid = threadIdx.x, wid = tid >> 5, lane = tid & 31;
    float* orow = out + (size_t)row * O_DIM;
    const float* urow = u + (size_t)row * O_DIM;
    __shared__ float red[16];
    __shared__ float bval;

    // ---- big segment: off=205, n=711 ----
    float y[3];
    float lmax = -3.4e38f;
#pragma unroll
    for (int it = 0; it < 3; it++) {
        const int i = tid + it * 288;
        if (i < 711) {
            const float v = (orow[205 + i] + gumbel_g(urow[205 + i])) * 1.25f;
            y[it] = v;
            lmax = fmaxf(lmax, v);
        } else y[it] = -3.4e38f;
    }
#pragma unroll
    for (int o = 16; o > 0; o >>= 1) lmax = fmaxf(lmax, __shfl_xor_sync(~0u, lmax, o));
    if (lane == 0) red[wid] = lmax;
    __syncthreads();
    if (tid < 32) {
        float w = (lane < 9) ? red[lane] : -3.4e38f;
#pragma unroll
        for (int o = 8; o > 0; o >>= 1) w = fmaxf(w, __shfl_xor_sync(~0u, w, o));
        if (lane == 0) bval = w;
    }
    __syncthreads();
    const float m = bval;
    float lsum = 0.f;
#pragma unroll
    for (int it = 0; it < 3; it++) {
        const int i = tid + it * 288;
        if (i < 711) { const float e = __expf(y[it] - m); y[it] = e; lsum += e; }
    }
#pragma unroll
    for (int o = 16; o > 0; o >>= 1) lsum += __shfl_xor_sync(~0u, lsum, o);
    if (lane == 0) red[wid] = lsum;
    __syncthreads();
    if (tid < 32) {
        float w = (lane < 9) ? red[lane] : 0.f;
#pragma unroll
        for (int o = 8; o > 0; o >>= 1) w += __shfl_xor_sync(~0u, w, o);
        if (lane == 0) bval = w;
    }
    __syncthreads();
    const float inv = 1.f / bval;
#pragma unroll
    for (int it = 0; it < 3; it++) {
        const int i = tid + it * 288;
        if (i < 711) orow[205 + i] = y[it] * inv;
    }

    // ---- small segments: warp `wid` handles segment `wid` ----
    {
        const int off = c_soff[wid], n = c_snum[wid];
        float z[3];
        float wmax = -3.4e38f;
#pragma unroll
        for (int it = 0; it < 3; it++) {
            const int i = lane + it * 32;
            if (i < n) {
                const float v = (orow[off + i] + gumbel_g(urow[off + i])) * 1.25f;
                z[it] = v;
                wmax = fmaxf(wmax, v);
            } else z[it] = -3.4e38f;
        }
#pragma unroll
        for (int o = 16; o > 0; o >>= 1) wmax = fmaxf(wmax, __shfl_xor_sync(~0u, wmax, o));
        float wsum = 0.f;
#pragma unroll
        for (int it = 0; it < 3; it++) {
            const int i = lane + it * 32;
            if (i < n) { const float e = __expf(z[it] - wmax); z[it] = e; wsum += e; }
        }
#pragma unroll
        for (int o = 16; o > 0; o >>= 1) wsum += __shfl_xor_sync(~0u, wsum, o);
        const float winv = 1.f / wsum;
#pragma unroll
        for (int it = 0; it < 3; it++) {
            const int i = lane + it * 32;
            if (i < n) orow[off + i] = z[it] * winv;
        }
    }
}

// ---------------------------------------------------------------------------
// Launch
// ---------------------------------------------------------------------------
extern "C" void kernel_launch(void* const* d_in, const int* in_sizes, int n_in,
                              void* d_out, int out_size)
{
    const float* x  = (const float*)d_in[0];
    const float* W1 = (const float*)d_in[1];
    const float* b1 = (const float*)d_in[2];
    const float* W2 = (const float*)d_in[3];
    const float* b2 = (const float*)d_in[4];
    const float* W3 = (const float*)d_in[5];
    const float* b3 = (const float*)d_in[6];
    const float* u  = (const float*)d_in[7];
    float* out = (float*)d_out;

    __half *x16, *h1, *h2, *w1t, *w2t, *w3t;
    cudaGetSymbolAddress((void**)&x16, g_x16);
    cudaGetSymbolAddress((void**)&h1,  g_h1);
    cudaGetSymbolAddress((void**)&h2,  g_h2);
    cudaGetSymbolAddress((void**)&w1t, g_w1t);
    cudaGetSymbolAddress((void**)&w2t, g_w2t);
    cudaGetSymbolAddress((void**)&w3t, g_w3t);

    cudaFuncSetAttribute(gemm_mma<1, true>,  cudaFuncAttributeMaxDynamicSharedMemorySize, GEMM_SMEM_BYTES);
    cudaFuncSetAttribute(gemm_mma<2, true>,  cudaFuncAttributeMaxDynamicSharedMemorySize, GEMM_SMEM_BYTES);
    cudaFuncSetAttribute(gemm_mma<0, false>, cudaFuncAttributeMaxDynamicSharedMemorySize, GEMM_SMEM_BYTES);

    // input / weight preparation
    convert_x_kernel<<<(M_ROWS * 128 + 255) / 256, 256>>>(x, x16, M_ROWS * 128);
    dim3 tsb(32, 8);
    transpose_h_kernel<<<dim3(32, 4),  tsb>>>(W1, 128,  1024, w1t);
    transpose_h_kernel<<<dim3(32, 32), tsb>>>(W2, 1024, 1024, w2t);
    transpose_h_kernel<<<dim3(32, 32), tsb>>>(W3, 1024, 929,  w3t);

    dim3 grid(8, 256), block(256);
    // h1 = elu(x @ W1 + b1), fp16
    gemm_mma<1, true><<<grid, block, GEMM_SMEM_BYTES>>>(
        x16, w1t, b1, nullptr, h1, H_DIM, 128);
    // h2 = sigmoid(h1 @ W2 + b2), fp16
    gemm_mma<2, true><<<grid, block, GEMM_SMEM_BYTES>>>(
        h1, w2t, b2, nullptr, h2, H_DIM, H_DIM);
    // logits = h2 @ W3 + b3, fp32 to d_out
    gemm_mma<0, false><<<grid, block, GEMM_SMEM_BYTES>>>(
        h2, w3t, b3, out, nullptr, O_DIM, H_DIM);
    // segmented gumbel softmax in place
    gumbel_softmax2<<<M_ROWS, 288>>>(out, u);
}

// round 12
// speedup vs baseline: 5.6495x; 1.0032x over previous
#include <cuda_runtime.h>
#include <cuda_fp16.h>
#include <math.h>
#include <stdint.h>

#define M_ROWS 32768
#define H_DIM  1024
#define O_DIM  929
#define EPS_G  1e-20f

// ---------------------------------------------------------------------------
// Scratch (static device globals; no allocation allowed)
// ---------------------------------------------------------------------------
__device__ __align__(16) __half g_x16[(size_t)M_ROWS * 128];
__device__ __align__(16) __half g_h1[(size_t)M_ROWS * H_DIM];
__device__ __align__(16) __half g_h2[(size_t)M_ROWS * H_DIM];
__device__ __align__(16) __half g_w1t[1024 * 128];
__device__ __align__(16) __half g_w2t[1024 * 1024];
__device__ __align__(16) __half g_w3t[1024 * 1024];

// ---------------------------------------------------------------------------
// PTX helpers (sm_80-era, target-portable)
// ---------------------------------------------------------------------------
static __device__ __forceinline__ uint32_t smem_to_u32(const void* p) {
    uint32_t a;
    asm("{ .reg .u64 t; cvta.to.shared.u64 t, %1; cvt.u32.u64 %0, t; }"
        : "=r"(a) : "l"(p));
    return a;
}

#define CP_ASYNC16(dst, src) \
    asm volatile("cp.async.cg.shared.global [%0], [%1], 16;" :: "r"(dst), "l"(src))
#define CP_COMMIT() asm volatile("cp.async.commit_group;")
#define CP_WAIT1()  asm volatile("cp.async.wait_group 1;")
#define CP_WAIT0()  asm volatile("cp.async.wait_group 0;")

#define LDMX4(r, a) \
    asm volatile("ldmatrix.sync.aligned.m8n8.x4.shared.b16 {%0,%1,%2,%3}, [%4];" \
        : "=r"((r)[0]), "=r"((r)[1]), "=r"((r)[2]), "=r"((r)[3]) : "r"(a))

static __device__ __forceinline__ void mma16816(float* c, const uint32_t* a,
                                                uint32_t b0, uint32_t b1) {
    asm volatile(
        "mma.sync.aligned.m16n8k16.row.col.f32.f16.f16.f32 "
        "{%0,%1,%2,%3}, {%4,%5,%6,%7}, {%8,%9}, {%0,%1,%2,%3};"
        : "+f"(c[0]), "+f"(c[1]), "+f"(c[2]), "+f"(c[3])
        : "r"(a[0]), "r"(a[1]), "r"(a[2]), "r"(a[3]), "r"(b0), "r"(b1));
}

#define SWZ(o) ((o) ^ ((((uint32_t)(o)) >> 3) & 0x70))

// ---------------------------------------------------------------------------
// x convert: fp32 -> fp16
// ---------------------------------------------------------------------------
__global__ void convert_x_kernel(const float* __restrict__ x,
                                 __half* __restrict__ x16, int n)
{
    const int i = blockIdx.x * blockDim.x + threadIdx.x;
    if (i < n) x16[i] = __float2half(x[i]);
}

// ---------------------------------------------------------------------------
// Weight transpose: W [K,N] fp32 -> T [Npad,K] fp16 (rows >= N zero-filled)
// ---------------------------------------------------------------------------
__global__ void transpose_h_kernel(const float* __restrict__ W, int K, int N,
                                   __half* __restrict__ T)
{
    __shared__ float t[32][33];
    const int n0 = blockIdx.x * 32, k0 = blockIdx.y * 32;
    const int tx = threadIdx.x, ty = threadIdx.y;
#pragma unroll
    for (int j = 0; j < 32; j += 8) {
        const int k = k0 + ty + j, n = n0 + tx;
        t[ty + j][tx] = (n < N) ? W[(size_t)k * N + n] : 0.f;
    }
    __syncthreads();
#pragma unroll
    for (int j = 0; j < 32; j += 8) {
        const int n = n0 + ty + j, k = k0 + tx;
        T[(size_t)n * K + k] = __float2half(t[tx][ty + j]);
    }
}

// ---------------------------------------------------------------------------
// fp16 HMMA GEMM: C[M,Nlog] = act(A @ Bt^T + bias)
//   A  : fp16 [M,K] row-major (K contig)
//   Bt : fp16 [Npad,K] (K contig), Npad = gridDim.x*128
// BM=BN=128, BK=64, 256 threads, 8 warps (4m x 2n), warp tile 32x64.
// Triple-buffered cp.async, ONE barrier per stage, SW128 swizzle.
// __launch_bounds__(256, 2): 2 CTAs/SM (2 x 96 KB smem fits in 228 KB;
// reg cap 128/thread) so one CTA's MMA work hides the other's bubbles.
// ACT: 0 none, 1 ELU, 2 sigmoid.  HALF_OUT: write fp16, else fp32.
// ---------------------------------------------------------------------------
#define STAGE_BYTES 32768
#define GEMM_SMEM_BYTES (3 * STAGE_BYTES)

template <int ACT, bool HALF_OUT>
__global__ __launch_bounds__(256, 2)
void gemm_mma(const __half* __restrict__ A,
              const __half* __restrict__ B,
              const float* __restrict__ bias,
              float* __restrict__ Cf,
              __half* __restrict__ Ch,
              int Nlog, int K)
{
    extern __shared__ char smem[];
    const uint32_t sm0 = smem_to_u32(smem);

    const int tid = threadIdx.x, wid = tid >> 5, lane = tid & 31;
    const int m0 = blockIdx.y * 128, n0 = blockIdx.x * 128;
    const int wm = (wid & 3) * 32;     // warp m offset in tile
    const int wn = (wid >> 2) * 64;    // warp n offset in tile

    const __half* gA = A + (size_t)m0 * K;
    const __half* gB = B + (size_t)n0 * K;

    // 1024 16B chunks per operand part; thread t covers ci = 4t..4t+3
    const int ci0 = tid << 2;

    auto load_stage = [&](int s, int buf) {
        const int k0 = s << 6;
        const uint32_t sb = sm0 + buf * STAGE_BYTES;
#pragma unroll
        for (int j = 0; j < 4; j++) {
            const int ci  = ci0 + j;
            const int row = ci >> 3, ch = ci & 7;
            const uint32_t dst = SWZ((uint32_t)(row * 128 + ch * 16));
            const size_t   go  = (size_t)row * K + k0 + ch * 8;
            CP_ASYNC16(sb + dst,         gA + go);
            CP_ASYNC16(sb + 16384 + dst, gB + go);
        }
        CP_COMMIT();
    };

    float c[16][4];
#pragma unroll
    for (int i = 0; i < 16; i++)
#pragma unroll
        for (int j = 0; j < 4; j++) c[i][j] = 0.f;

    const int nst = K >> 6;
    // prologue: stages 0 and 1 in flight
    load_stage(0, 0);
    if (nst > 1) load_stage(1, 1);

    const int lrow = lane & 15;          // ldmatrix row within 16-row group
    const int lch  = (lane >> 4) << 4;   // 0 or 16 bytes (k sub-chunk)

    int buf = 0;                          // buf = s % 3
    for (int s = 0; s < nst; s++) {
        // stage s must be complete:
        if (s + 1 < nst) { CP_WAIT1(); }
        else             { CP_WAIT0(); }
        __syncthreads();   // ALSO releases buffer (s+2)%3 (= (s-1)%3) for reuse

        // issue stage s+2 into buffer (s+2)%3 — safe after the barrier
        if (s + 2 < nst) {
            int nb = buf + 2; if (nb >= 3) nb -= 3;
            load_stage(s + 2, nb);
        }

        const uint32_t sb = sm0 + buf * STAGE_BYTES;
#pragma unroll
        for (int kk = 0; kk < 4; kk++) {
            uint32_t a[2][4], b[4][4];
#pragma unroll
            for (int am = 0; am < 2; am++) {
                const uint32_t o = SWZ((uint32_t)((wm + am * 16 + lrow) * 128 + kk * 32 + lch));
                LDMX4(a[am], sb + o);
            }
#pragma unroll
            for (int g = 0; g < 4; g++) {
                const uint32_t o = SWZ((uint32_t)((wn + g * 16 + lrow) * 128 + kk * 32 + lch));
                LDMX4(b[g], sb + 16384 + o);
            }
#pragma unroll
            for (int am = 0; am < 2; am++)
#pragma unroll
                for (int nb2 = 0; nb2 < 8; nb2++) {
                    const int g = nb2 >> 1, s2 = nb2 & 1;
                    mma16816(c[am * 8 + nb2], a[am], b[g][s2], b[g][s2 + 2]);
                }
        }
        if (++buf == 3) buf = 0;
    }

    // epilogue: bias + activation
    const int g  = lane >> 2;
    const int tg = (lane & 3) << 1;
#pragma unroll
    for (int am = 0; am < 2; am++) {
        const int rbase = m0 + wm + am * 16 + g;
#pragma unroll
        for (int nb = 0; nb < 8; nb++) {
            const int col = n0 + wn + nb * 8 + tg;
            const float bi0 = __ldg(bias + col);
            const float bi1 = __ldg(bias + col + 1);
            float* cc = c[am * 8 + nb];
#pragma unroll
            for (int h = 0; h < 2; h++) {
                const int row = rbase + h * 8;
                float v0 = cc[h * 2 + 0] + bi0;
                float v1 = cc[h * 2 + 1] + bi1;
                if (ACT == 1) {
                    v0 = (v0 > 0.f) ? v0 : (__expf(v0) - 1.f);
                    v1 = (v1 > 0.f) ? v1 : (__expf(v1) - 1.f);
                } else if (ACT == 2) {
                    v0 = 1.f / (1.f + __expf(-v0));
                    v1 = 1.f / (1.f + __expf(-v1));
                }
                if (HALF_OUT) {
                    const size_t off = (size_t)row * Nlog + col;
                    *(__half2*)(Ch + off) = __floats2half2_rn(v0, v1);
                } else {
                    const size_t off = (size_t)row * Nlog + col;
                    if (col < Nlog)     Cf[off]     = v0;
                    if (col + 1 < Nlog) Cf[off + 1] = v1;
                }
            }
        }
    }
}

// ---------------------------------------------------------------------------
// Gumbel helper: g = -log(-log(u + eps) + eps)
// Inner log: MUFU fast path unless u > 0.99 (where |ln u| -> 0 makes MUFU's
// absolute error blow up relatively); outer log: always MUFU (abs err ~1.6e-7).
// ---------------------------------------------------------------------------
static __device__ __forceinline__ float gumbel_g(float u)
{
    const float up = u + EPS_G;
    float t;
    if (up <= 0.99f) t = -__logf(up);
    else             t = -logf(up);
    return -__logf(t + EPS_G);
}

// ---------------------------------------------------------------------------
// Gumbel softmax: one 288-thread block (9 warps) per row.
// Big segment (off=205, n=711): block-cooperative (2 block reductions).
// 9 small segments: one warp each, shfl-only reductions.
// ---------------------------------------------------------------------------
__constant__ int c_soff[9] = {0, 29, 32, 38, 45, 105, 129, 916, 919};
__constant__ int c_snum[9] = {29, 2, 6, 7, 59, 24, 76, 3, 9};

__global__ __launch_bounds__(288)
void gumbel_softmax2(float* __restrict__ out, const float* __restrict__ u)
{
    const int row = blockIdx.x, tid = threadIdx.x, wid = tid >> 5, lane = tid & 31;
    float* orow = out + (size_t)row * O_DIM;
    const float* urow = u + (size_t)row * O_DIM;
    __shared__ float red[16];
    __shared__ float bval;

    // ---- big segment: off=205, n=711 ----
    float y[3];
    float lmax = -3.4e38f;
#pragma unroll
    for (int it = 0; it < 3; it++) {
        const int i = tid + it * 288;
        if (i < 711) {
            const float v = (orow[205 + i] + gumbel_g(urow[205 + i])) * 1.25f;
            y[it] = v;
            lmax = fmaxf(lmax, v);
        } else y[it] = -3.4e38f;
    }
#pragma unroll
    for (int o = 16; o > 0; o >>= 1) lmax = fmaxf(lmax, __shfl_xor_sync(~0u, lmax, o));
    if (lane == 0) red[wid] = lmax;
    __syncthreads();
    if (tid < 32) {
        float w = (lane < 9) ? red[lane] : -3.4e38f;
#pragma unroll
        for (int o = 8; o > 0; o >>= 1) w = fmaxf(w, __shfl_xor_sync(~0u, w, o));
        if (lane == 0) bval = w;
    }
    __syncthreads();
    const float m = bval;
    float lsum = 0.f;
#pragma unroll
    for (int it = 0; it < 3; it++) {
        const int i = tid + it * 288;
        if (i < 711) { const float e = __expf(y[it] - m); y[it] = e; lsum += e; }
    }
#pragma unroll
    for (int o = 16; o > 0; o >>= 1) lsum += __shfl_xor_sync(~0u, lsum, o);
    if (lane == 0) red[wid] = lsum;
    __syncthreads();
    if (tid < 32) {
        float w = (lane < 9) ? red[lane] : 0.f;
#pragma unroll
        for (int o = 8; o > 0; o >>= 1) w += __shfl_xor_sync(~0u, w, o);
        if (lane == 0) bval = w;
    }
    __syncthreads();
    const float inv = 1.f / bval;
#pragma unroll
    for (int it = 0; it < 3; it++) {
        const int i = tid + it * 288;
        if (i < 711) orow[205 + i] = y[it] * inv;
    }

    // ---- small segments: warp `wid` handles segment `wid` ----
    {
        const int off = c_soff[wid], n = c_snum[wid];
        float z[3];
        float wmax = -3.4e38f;
#pragma unroll
        for (int it = 0; it < 3; it++) {
            const int i = lane + it * 32;
            if (i < n) {
                const float v = (orow[off + i] + gumbel_g(urow[off + i])) * 1.25f;
                z[it] = v;
                wmax = fmaxf(wmax, v);
            } else z[it] = -3.4e38f;
        }
#pragma unroll
        for (int o = 16; o > 0; o >>= 1) wmax = fmaxf(wmax, __shfl_xor_sync(~0u, wmax, o));
        float wsum = 0.f;
#pragma unroll
        for (int it = 0; it < 3; it++) {
            const int i = lane + it * 32;
            if (i < n) { const float e = __expf(z[it] - wmax); z[it] = e; wsum += e; }
        }
#pragma unroll
        for (int o = 16; o > 0; o >>= 1) wsum += __shfl_xor_sync(~0u, wsum, o);
        const float winv = 1.f / wsum;
#pragma unroll
        for (int it = 0; it < 3; it++) {
            const int i = lane + it * 32;
            if (i < n) orow[off + i] = z[it] * winv;
        }
    }
}

// ---------------------------------------------------------------------------
// Launch
// ---------------------------------------------------------------------------
extern "C" void kernel_launch(void* const* d_in, const int* in_sizes, int n_in,
                              void* d_out, int out_size)
{
    const float* x  = (const float*)d_in[0];
    const float* W1 = (const float*)d_in[1];
    const float* b1 = (const float*)d_in[2];
    const float* W2 = (const float*)d_in[3];
    const float* b2 = (const float*)d_in[4];
    const float* W3 = (const float*)d_in[5];
    const float* b3 = (const float*)d_in[6];
    const float* u  = (const float*)d_in[7];
    float* out = (float*)d_out;

    __half *x16, *h1, *h2, *w1t, *w2t, *w3t;
    cudaGetSymbolAddress((void**)&x16, g_x16);
    cudaGetSymbolAddress((void**)&h1,  g_h1);
    cudaGetSymbolAddress((void**)&h2,  g_h2);
    cudaGetSymbolAddress((void**)&w1t, g_w1t);
    cudaGetSymbolAddress((void**)&w2t, g_w2t);
    cudaGetSymbolAddress((void**)&w3t, g_w3t);

    cudaFuncSetAttribute(gemm_mma<1, true>,  cudaFuncAttributeMaxDynamicSharedMemorySize, GEMM_SMEM_BYTES);
    cudaFuncSetAttribute(gemm_mma<2, true>,  cudaFuncAttributeMaxDynamicSharedMemorySize, GEMM_SMEM_BYTES);
    cudaFuncSetAttribute(gemm_mma<0, false>, cudaFuncAttributeMaxDynamicSharedMemorySize, GEMM_SMEM_BYTES);

    // input / weight preparation
    convert_x_kernel<<<(M_ROWS * 128 + 255) / 256, 256>>>(x, x16, M_ROWS * 128);
    dim3 tsb(32, 8);
    transpose_h_kernel<<<dim3(32, 4),  tsb>>>(W1, 128,  1024, w1t);
    transpose_h_kernel<<<dim3(32, 32), tsb>>>(W2, 1024, 1024, w2t);
    transpose_h_kernel<<<dim3(32, 32), tsb>>>(W3, 1024, 929,  w3t);

    dim3 grid(8, 256), block(256);
    // h1 = elu(x @ W1 + b1), fp16
    gemm_mma<1, true><<<grid, block, GEMM_SMEM_BYTES>>>(
        x16, w1t, b1, nullptr, h1, H_DIM, 128);
    // h2 = sigmoid(h1 @ W2 + b2), fp16
    gemm_mma<2, true><<<grid, block, GEMM_SMEM_BYTES>>>(
        h1, w2t, b2, nullptr, h2, H_DIM, H_DIM);
    // logits = h2 @ W3 + b3, fp32 to d_out
    gemm_mma<0, false><<<grid, block, GEMM_SMEM_BYTES>>>(
        h2, w3t, b3, out, nullptr, O_DIM, H_DIM);
    // segmented gumbel softmax in place
    gumbel_softmax2<<<M_ROWS, 288>>>(out, u);
}